// round 2
// baseline (speedup 1.0000x reference)
#include <cuda_runtime.h>
#include <cstdint>

#define N_NODES   100000
#define N_EDGES   1600000
#define D         32
#define IN_FEAT   96
#define LATENT    32
#define OUT_FEAT  32

// L2-resident accumulator for segment_sum(edge_attr, receivers).
// 100000*32*4 = 12.8 MB — fits in the 126 MB L2. 16B-aligned for red.v4.
__device__ __align__(16) float g_agg[N_NODES * D];

// ---------------------------------------------------------------------------
// Kernel 1: zero the accumulator (re-zeroed every graph replay)
// ---------------------------------------------------------------------------
__global__ void zero_agg_kernel() {
    int i = blockIdx.x * blockDim.x + threadIdx.x;
    float4* p = reinterpret_cast<float4*>(g_agg);
    const int n = (N_NODES * D) / 4;
    if (i < n) p[i] = make_float4(0.f, 0.f, 0.f, 0.f);
}

// ---------------------------------------------------------------------------
// Kernel 2: scatter-add edge features by receiver.
// 8 threads per edge; each thread owns one float4 chunk and issues a single
// vectorized L2 reduction (red.global.add.v4.f32) — 4x fewer atomic messages
// than scalar atomicAdd. Indices arrive as int32 (harness converts int64).
// ---------------------------------------------------------------------------
__global__ void scatter_kernel(const float* __restrict__ edge_attr,
                               const int* __restrict__ receivers) {
    int tid = blockIdx.x * blockDim.x + threadIdx.x;
    if (tid >= N_EDGES * 8) return;
    int e = tid >> 3;
    int c = tid & 7;

    int r = receivers[e];                 // broadcast within 8-thread group
    if ((unsigned)r >= N_NODES) return;   // defensive: clean fail, not fault

    float4 v = reinterpret_cast<const float4*>(edge_attr)[e * 8 + c];

    float* dst = g_agg + (size_t)r * D + c * 4;
    asm volatile("red.global.add.v4.f32 [%0], {%1, %2, %3, %4};"
                 :: "l"(dst), "f"(v.x), "f"(v.y), "f"(v.z), "f"(v.w)
                 : "memory");
}

// ---------------------------------------------------------------------------
// Kernel 3: fused concat + 2-layer MLP.
// One thread per node. Weights in shared (broadcast reads). Node inputs
// staged in shared with stride-97 rows (conflict-free: lane*97+k mod 32 is a
// permutation). The global-attr + b1 contribution to layer 1 is node-invariant
// and precomputed once per block into gb[] — cuts layer-1 FMAs by 1/3.
// ---------------------------------------------------------------------------
#define TPB 128
#define XS  97   // 64 staged features + padding (stride 97 => conflict-free)

__global__ __launch_bounds__(TPB) void mlp_kernel(
    const float* __restrict__ node_attr,
    const float* __restrict__ global_attr,
    const float* __restrict__ W1, const float* __restrict__ b1,
    const float* __restrict__ W2, const float* __restrict__ b2,
    float* __restrict__ out)
{
    __shared__ float xs[TPB * XS];               // [node, agg] per local node
    __shared__ float w1s[IN_FEAT * LATENT];      // 96x32
    __shared__ float w2s[LATENT * OUT_FEAT];     // 32x32
    __shared__ float b2s[OUT_FEAT];
    __shared__ float gb[LATENT];                 // b1 + global@W1[64:96]

    const int tid  = threadIdx.x;
    const int base = blockIdx.x * TPB;
    const int nvalid = min(TPB, N_NODES - base);

    // Stage weights
    for (int i = tid; i < IN_FEAT * LATENT; i += TPB) w1s[i] = W1[i];
    for (int i = tid; i < LATENT * OUT_FEAT; i += TPB) w2s[i] = W2[i];
    if (tid < OUT_FEAT) b2s[tid] = b2[tid];

    // Stage node_attr and agg for this block's nodes (coalesced reads)
    for (int i = tid; i < nvalid * D; i += TPB) {
        int nl = i >> 5, k = i & 31;
        xs[nl * XS + k]      = node_attr[(base + nl) * D + k];
        xs[nl * XS + 32 + k] = g_agg[(base + nl) * D + k];
    }
    __syncthreads();

    // gb[j] = b1[j] + sum_k g[k]*W1[64+k][j]  (node-invariant)
    if (tid < LATENT) {
        float acc = b1[tid];
        #pragma unroll
        for (int k = 0; k < D; k++)
            acc = fmaf(global_attr[k], w1s[(64 + k) * LATENT + tid], acc);
        gb[tid] = acc;
    }
    __syncthreads();

    // Layer 1: h = relu([node, agg] @ W1[0:64] + gb)
    float h[LATENT];
    #pragma unroll
    for (int j = 0; j < LATENT; j++) h[j] = gb[j];

    const float* xrow = &xs[tid * XS];
    #pragma unroll 4
    for (int k = 0; k < 64; k++) {
        float xk = xrow[k];
        #pragma unroll
        for (int j = 0; j < LATENT; j++)
            h[j] = fmaf(xk, w1s[k * LATENT + j], h[j]);
    }
    #pragma unroll
    for (int j = 0; j < LATENT; j++) h[j] = fmaxf(h[j], 0.f);

    // Layer 2: o = h @ W2 + b2
    float o[OUT_FEAT];
    #pragma unroll
    for (int j = 0; j < OUT_FEAT; j++) o[j] = b2s[j];
    #pragma unroll
    for (int i = 0; i < LATENT; i++) {
        float hi = h[i];
        #pragma unroll
        for (int j = 0; j < OUT_FEAT; j++)
            o[j] = fmaf(hi, w2s[i * OUT_FEAT + j], o[j]);
    }

    // Store (vectorized; per-thread contiguous row)
    if (tid < nvalid) {
        float4* dst = reinterpret_cast<float4*>(out + (size_t)(base + tid) * OUT_FEAT);
        #pragma unroll
        for (int j = 0; j < OUT_FEAT / 4; j++)
            dst[j] = make_float4(o[4 * j], o[4 * j + 1], o[4 * j + 2], o[4 * j + 3]);
    }
}

// ---------------------------------------------------------------------------
// Launch. Input order (metadata): node_attr, edge_index (int64 -> int32 on
// device), edge_attr, global_attr, W1, b1, W2, b2. Output: float32 [100000,32].
// ---------------------------------------------------------------------------
extern "C" void kernel_launch(void* const* d_in, const int* in_sizes, int n_in,
                              void* d_out, int out_size) {
    const float* node_attr   = (const float*)d_in[0];
    const int*   edge_index  = (const int*)d_in[1];
    const float* edge_attr   = (const float*)d_in[2];
    const float* global_attr = (const float*)d_in[3];
    const float* W1          = (const float*)d_in[4];
    const float* b1          = (const float*)d_in[5];
    const float* W2          = (const float*)d_in[6];
    const float* b2          = (const float*)d_in[7];
    float*       out         = (float*)d_out;

    const int* receivers = edge_index + N_EDGES;  // edge_index[1]

    // 1) zero accumulator
    {
        int n = (N_NODES * D) / 4;
        zero_agg_kernel<<<(n + 255) / 256, 256>>>();
    }
    // 2) scatter-add edges
    {
        int n = N_EDGES * 8;
        scatter_kernel<<<(n + 255) / 256, 256>>>(edge_attr, receivers);
    }
    // 3) fused concat + MLP
    {
        int blocks = (N_NODES + TPB - 1) / TPB;
        mlp_kernel<<<blocks, TPB>>>(node_attr, global_attr, W1, b1, W2, b2, out);
    }
    (void)in_sizes; (void)n_in; (void)out_size;
}